// round 5
// baseline (speedup 1.0000x reference)
#include <cuda_runtime.h>
#include <math.h>
#include <cstdint>

#define THREADS 128

typedef unsigned long long u64;
typedef unsigned int u32;

// ---------------- f32x2 helpers ----------------
__device__ __forceinline__ u64 ffma2(u64 a, u64 b, u64 c) {
    u64 d; asm("fma.rn.f32x2 %0, %1, %2, %3;" : "=l"(d) : "l"(a), "l"(b), "l"(c)); return d;
}
__device__ __forceinline__ u64 mul2(u64 a, u64 b) {
    u64 d; asm("mul.rn.f32x2 %0, %1, %2;" : "=l"(d) : "l"(a), "l"(b)); return d;
}
__device__ __forceinline__ u64 add2(u64 a, u64 b) {
    u64 d; asm("add.rn.f32x2 %0, %1, %2;" : "=l"(d) : "l"(a), "l"(b)); return d;
}
__device__ __forceinline__ u64 dup2(float x) {
    u64 d; unsigned u = __float_as_uint(x);
    asm("mov.b64 %0, {%1, %2};" : "=l"(d) : "r"(u), "r"(u)); return d;
}
__device__ __forceinline__ u64 pack2(float a, float b) {
    u64 d; asm("mov.b64 %0, {%1, %2};" : "=l"(d) : "r"(__float_as_uint(a)), "r"(__float_as_uint(b))); return d;
}
__device__ __forceinline__ void unpack2(u64 v, float &lo, float &hi) {
    unsigned a, b; asm("mov.b64 {%0, %1}, %2;" : "=r"(a), "=r"(b) : "l"(v));
    lo = __uint_as_float(a); hi = __uint_as_float(b);
}
__device__ __forceinline__ u32 f2tf32(float f) {
    u32 r; asm("cvt.rna.tf32.f32 %0, %1;" : "=r"(r) : "f"(f)); return r;
}

// mma.sync m16n8k8 tf32
__device__ __forceinline__ void mma8(float* acc, u32 a0, u32 a1, u32 a2, u32 a3, u64 b) {
    u32 b0 = (u32)b, b1 = (u32)(b >> 32);
    asm volatile("mma.sync.aligned.m16n8k8.row.col.f32.tf32.tf32.f32 "
                 "{%0,%1,%2,%3}, {%4,%5,%6,%7}, {%8,%9}, {%0,%1,%2,%3};"
                 : "+f"(acc[0]), "+f"(acc[1]), "+f"(acc[2]), "+f"(acc[3])
                 : "r"(a0), "r"(a1), "r"(a2), "r"(a3), "r"(b0), "r"(b1));
}

__device__ __forceinline__ float qredf(float v) {
    v += __shfl_xor_sync(0xffffffffu, v, 1);
    v += __shfl_xor_sync(0xffffffffu, v, 2);
    return v;
}

// ---------------- smem layout (bytes) ----------------
#define SM_XY    0        /* float2[128]                 1024 */
#define SM_SF    1024     /* float4[128]                 2048 */
#define SM_Q     3072     /* float4[128]                 2048 */
#define SM_RES   5120     /* float4[128]                 2048 */
#define SM_META  7168     /* 128 jp x 4 ulonglong2       8192 */
#define SM_W2C   15360    /* ulonglong2[64]              1024 */
#define SM_A     16384    /* u64 pairs [128][32] swz     32768 */
#define SM_BP    49152    /* ulonglong2 [256][16] swz    65536 */
#define SMEM_BYTES 114688

#define LK_A 0.84852813742385703f  /* 0.6*sqrt(2) */
#define LK_B 0.56568542494923801f  /* 0.4*sqrt(2) */

__global__ __launch_bounds__(THREADS, 2)
void coupling_mma_kernel(const float* __restrict__ coords,
                         const float* __restrict__ c,
                         const float* __restrict__ Wx1, const float* __restrict__ bx1,
                         const float* __restrict__ Wx2, const float* __restrict__ bx2,
                         const float* __restrict__ Wy1, const float* __restrict__ by1,
                         const float* __restrict__ Wy2, const float* __restrict__ by2,
                         float* __restrict__ out, long M)
{
    extern __shared__ char smem[];
    const int tid  = threadIdx.x;
    const int lane = tid & 31;
    const int warp = tid >> 5;
    const int g    = lane >> 2;     // 0..7
    const int tq   = lane & 3;      // 0..3

    const float s1 = 1.0f / sqrtf(68.0f);
    const float s2 = 1.0f / sqrtf(192.0f);

    float2* XY = (float2*)(smem + SM_XY);
    float4* SF = (float4*)(smem + SM_SF);
    float4* QS = (float4*)(smem + SM_Q);
    float4* RES = (float4*)(smem + SM_RES);
    ulonglong2* MPV = (ulonglong2*)(smem + SM_META);
    ulonglong2* W2C = (ulonglong2*)(smem + SM_W2C);
    u64*    APV = (u64*)(smem + SM_A);
    ulonglong2* BPV = (ulonglong2*)(smem + SM_BP);

    // ================= weight staging (once per CTA) =================
    // BP: per n (0..255), slot s (0..15): j' = s>>2, tqs = s&3, j = j'^(n&1)
    //     holds { pair(kk=2j), pair(kk=2j+1) } for column tqs
    #pragma unroll
    for (int i = 0; i < 32; i++) {
        int idx = tid + i * THREADS;            // ulonglong2 index 0..4095
        int n   = idx >> 4;
        int s   = idx & 15;
        int jj  = (s >> 2) ^ (n & 1);
        int tqs = s & 3;
        const float* Wg = (n < 128) ? Wx1 : Wy1;
        int row = n & 127;
        int k0 = jj * 16 + tqs;                 // = (2j)*8 + tqs
        const float* wr = Wg + row * 68 + 4;
        ulonglong2 v;
        v.x = ((u64)f2tf32(wr[k0 + 4]  * s1) << 32) | f2tf32(wr[k0]      * s1);
        v.y = ((u64)f2tf32(wr[k0 + 12] * s1) << 32) | f2tf32(wr[k0 + 8]  * s1);
        BPV[idx] = v;
    }
    // meta: jp = output-pair index (0..127). 4 ulonglong2 slots, slot p at p^(jp&3):
    //   p0=(A0,A1) p1=(A2,A3) p2=(H0,H1) p3=(BB,0)
    {
        int jp = tid;
        int j0 = 2 * jp;
        int st = j0 >> 7;
        int jj0 = j0 & 127, jj1 = jj0 + 1;
        const float* W1g = st ? Wy1 : Wx1;
        const float* W2g = st ? Wy2 : Wx2;
        const float* b1g = st ? by1 : bx1;
        int sw = jp & 3;
        ulonglong2* mp = MPV + jp * 4;
        ulonglong2 p0, p1, p2, p3;
        p0.x = pack2(W1g[jj0 * 68 + 0] * s1, W1g[jj1 * 68 + 0] * s1);
        p0.y = pack2(W1g[jj0 * 68 + 1] * s1, W1g[jj1 * 68 + 1] * s1);
        p1.x = pack2(W1g[jj0 * 68 + 2] * s1, W1g[jj1 * 68 + 2] * s1);
        p1.y = pack2(W1g[jj0 * 68 + 3] * s1, W1g[jj1 * 68 + 3] * s1);
        p2.x = pack2(W2g[jj0] * s2, W2g[jj1] * s2);
        p2.y = pack2(W2g[192 + jj0] * s2, W2g[192 + jj1] * s2);
        p3.x = pack2(b1g[jj0], b1g[jj1]);
        p3.y = 0;
        mp[0 ^ sw] = p0; mp[1 ^ sw] = p1; mp[2 ^ sw] = p2; mp[3 ^ sw] = p3;
    }
    if (tid < 64) {
        int k = tid;
        ulonglong2 w;
        w.x = pack2(Wx2[128 + k] * s2, Wx2[192 + 128 + k] * s2);
        w.y = pack2(Wy2[128 + k] * s2, Wy2[192 + 128 + k] * s2);
        W2C[k] = w;
    }

    const u64 lkA = dup2(LK_A), lkB = dup2(LK_B);
    const u64 ABSM = 0x7FFFFFFF7FFFFFFFull;

    // ================= two row-tiles per CTA =================
    #pragma unroll 1
    for (int tile = 0; tile < 2; tile++) {
        const long base = (long)blockIdx.x * 256 + (long)tile * 128;
        __syncthreads();   // weights ready / previous tile fully consumed

        // ---- A staging: c[128x64] -> tf32 (k,k+4) u64 pairs, swizzled ----
        #pragma unroll
        for (int i = 0; i < 8; i++) {
            int idx = tid + i * THREADS;        // group 0..1023
            int row = idx >> 3;
            int kk  = idx & 7;
            long gr = base + row;
            float4 f0 = make_float4(0.f, 0.f, 0.f, 0.f), f1 = f0;
            if (gr < M) {
                f0 = *(const float4*)(c + gr * 64 + kk * 8);
                f1 = *(const float4*)(c + gr * 64 + kk * 8 + 4);
            }
            int swz = (row & 7) << 2;
            u64* ap = APV + row * 32;
            int pb = (kk * 4) ^ swz;            // t=0..3 consecutive after xor
            ap[pb + 0] = ((u64)f2tf32(f1.x) << 32) | f2tf32(f0.x);
            ap[pb + 1] = ((u64)f2tf32(f1.y) << 32) | f2tf32(f0.y);
            ap[pb + 2] = ((u64)f2tf32(f1.z) << 32) | f2tf32(f0.z);
            ap[pb + 3] = ((u64)f2tf32(f1.w) << 32) | f2tf32(f0.w);
        }
        // coords + stage-0 sin features (row = tid)
        {
            long rr = base + tid;
            float2 xy = make_float2(0.f, 0.f);
            if (rr < M) xy = ((const float2*)coords)[rr];
            XY[tid] = xy;
            float a = xy.x * 0.1f, sa, ca;
            sincosf(a, &sa, &ca);
            SF[tid] = make_float4(sa, 2.0f * sa * ca, ca, 1.0f - 2.0f * sa * sa);
        }
        __syncthreads();

        // ---- per-row q = c @ W2c (+ b2), row = tid ----
        {
            int row = tid;
            int swz = (row & 7) << 2;
            const u64* ap = APV + row * 32;
            u64 qx = pack2(0.f, 0.f), qy = qx;
            #pragma unroll
            for (int p = 0; p < 32; p++) {
                u64 pr = ap[p ^ swz];
                float c0, c1; unpack2(pr, c0, c1);
                int k0 = (p >> 2) * 8 + (p & 3);
                ulonglong2 w0 = W2C[k0];
                ulonglong2 w1 = W2C[k0 + 4];
                u64 d0 = dup2(c0), d1 = dup2(c1);
                qx = ffma2(d0, w0.x, qx); qy = ffma2(d0, w0.y, qy);
                qx = ffma2(d1, w1.x, qx); qy = ffma2(d1, w1.y, qy);
            }
            float qx0, qx1, qy0, qy1;
            unpack2(qx, qx0, qx1); unpack2(qy, qy0, qy1);
            QS[tid] = make_float4(qx0 + bx2[0], qx1 + bx2[1], qy0 + by2[0], qy1 + by2[1]);
        }
        __syncwarp();

        // ---- A fragments: uint2 per (mt,kk), rows r0 and r0+8 ----
        uint2 afL[2][8], afH[2][8];
        {
            const int swz = g << 2;
            #pragma unroll
            for (int mt = 0; mt < 2; mt++) {
                int r0 = warp * 32 + mt * 16 + g;
                const u64* apL = APV + r0 * 32;
                const u64* apH = APV + (r0 + 8) * 32;
                #pragma unroll
                for (int kk = 0; kk < 8; kk++) {
                    int p = (kk * 4 + tq) ^ swz;
                    u64 vL = apL[p], vH = apH[p];
                    afL[mt][kk] = make_uint2((u32)vL, (u32)(vL >> 32));
                    afH[mt][kk] = make_uint2((u32)vH, (u32)(vH >> 32));
                }
            }
        }

        int R[4];
        #pragma unroll
        for (int ri = 0; ri < 4; ri++) R[ri] = warp * 32 + ri * 8 + g;

        float cin[4], cup[4], lsum[4];
        #pragma unroll
        for (int ri = 0; ri < 4; ri++) {
            float2 xy = XY[R[ri]];
            cin[ri] = xy.x; cup[ri] = xy.y; lsum[ri] = 0.0f;
        }

        for (int st = 0; st < 2; st++) {
            float4 sfr[4];
            #pragma unroll
            for (int ri = 0; ri < 4; ri++) sfr[ri] = SF[R[ri]];

            u64 po0[4], po1[4];
            #pragma unroll
            for (int ri = 0; ri < 4; ri++) { po0[ri] = pack2(0.f, 0.f); po1[ri] = po0[ri]; }

            for (int chunk = 0; chunk < 4; chunk++) {
                int nbase = st * 16 + chunk * 4;
                float acc[2][4][4];
                #pragma unroll
                for (int mt = 0; mt < 2; mt++)
                    #pragma unroll
                    for (int nt = 0; nt < 4; nt++)
                        #pragma unroll
                        for (int q = 0; q < 4; q++) acc[mt][nt][q] = 0.0f;

                #pragma unroll
                for (int j = 0; j < 4; j++) {          // kk pairs (2j, 2j+1)
                    ulonglong2 bfr2[4];
                    #pragma unroll
                    for (int nt = 0; nt < 4; nt++) {
                        int n = (nbase + nt) * 8 + g;
                        bfr2[nt] = BPV[n * 16 + (((j ^ (n & 1)) << 2) | tq)];
                    }
                    #pragma unroll
                    for (int nt = 0; nt < 4; nt++) {
                        #pragma unroll
                        for (int mt = 0; mt < 2; mt++) {
                            uint2 aL0 = afL[mt][2 * j],     aH0 = afH[mt][2 * j];
                            uint2 aL1 = afL[mt][2 * j + 1], aH1 = afH[mt][2 * j + 1];
                            mma8(acc[mt][nt], aL0.x, aH0.x, aL0.y, aH0.y, bfr2[nt].x);
                            mma8(acc[mt][nt], aL1.x, aH1.x, aL1.y, aH1.y, bfr2[nt].y);
                        }
                    }
                }

                // fragment epilogue
                #pragma unroll
                for (int nt = 0; nt < 4; nt++) {
                    int jp = st * 64 + chunk * 16 + nt * 4 + tq;   // jp&3 == tq
                    const ulonglong2* mp = MPV + jp * 4;
                    ulonglong2 P0 = mp[0 ^ tq];
                    ulonglong2 P1 = mp[1 ^ tq];
                    ulonglong2 P2 = mp[2 ^ tq];
                    ulonglong2 P3 = mp[3 ^ tq];
                    u64 A0 = P0.x, A1 = P0.y, A2 = P1.x, A3 = P1.y;
                    u64 H0 = P2.x, H1 = P2.y, BB = P3.x;
                    #pragma unroll
                    for (int mt = 0; mt < 2; mt++) {
                        #pragma unroll
                        for (int h = 0; h < 2; h++) {
                            int ri = mt * 2 + h;
                            float4 sf = sfr[ri];
                            u64 v = pack2(acc[mt][nt][2 * h + 0], acc[mt][nt][2 * h + 1]);
                            v = add2(v, BB);
                            v = ffma2(dup2(sf.x), A0, v);
                            v = ffma2(dup2(sf.y), A1, v);
                            v = ffma2(dup2(sf.z), A2, v);
                            v = ffma2(dup2(sf.w), A3, v);
                            u64 av = v & ABSM;
                            u64 hh = ffma2(lkA, v, mul2(lkB, av));
                            po0[ri] = ffma2(hh, H0, po0[ri]);
                            po1[ri] = ffma2(hh, H1, po1[ri]);
                        }
                    }
                }
            }

            // reduce + coordinate update
            #pragma unroll
            for (int ri = 0; ri < 4; ri++) {
                float a0, a1, b0, b1;
                unpack2(po0[ri], a0, a1);
                unpack2(po1[ri], b0, b1);
                float o0 = qredf(a0 + a1);
                float o1 = qredf(b0 + b1);
                float4 qv = QS[R[ri]];
                o0 += st ? qv.z : qv.x;
                o1 += st ? qv.w : qv.y;
                float ls = fminf(fmaxf(o0, -5.0f), 5.0f);
                float up_new = cup[ri] * __expf(ls) + o1;
                lsum[ri] += ls;
                cup[ri] = cin[ri];
                cin[ri] = up_new;
            }

            if (st == 0) {
                #pragma unroll
                for (int ri = 0; ri < 4; ri++) {
                    float a = cin[ri] * 0.1f, sa, ca;
                    sincosf(a, &sa, &ca);
                    if (tq == 0)
                        SF[R[ri]] = make_float4(sa, 2.0f * sa * ca, ca, 1.0f - 2.0f * sa * sa);
                }
                __syncwarp();
            }
        }

        // after stage 1: cin = x_final, cup = y_final
        if (tq == 0) {
            #pragma unroll
            for (int ri = 0; ri < 4; ri++)
                RES[R[ri]] = make_float4(cin[ri], cup[ri], lsum[ri], 0.0f);
        }
        __syncthreads();

        long rr = base + tid;
        if (rr < M) {
            float4 rv = RES[tid];
            ((float2*)out)[rr] = make_float2(rv.x, rv.y);
            out[2 * M + rr] = rv.z;
        }
    }
}

extern "C" void kernel_launch(void* const* d_in, const int* in_sizes, int n_in,
                              void* d_out, int out_size) {
    const float* coords = (const float*)d_in[0];
    const float* c      = (const float*)d_in[1];
    const float* Wx1    = (const float*)d_in[2];
    const float* bx1    = (const float*)d_in[3];
    const float* Wx2    = (const float*)d_in[4];
    const float* bx2    = (const float*)d_in[5];
    const float* Wy1    = (const float*)d_in[6];
    const float* by1    = (const float*)d_in[7];
    const float* Wy2    = (const float*)d_in[8];
    const float* by2    = (const float*)d_in[9];
    float* out = (float*)d_out;

    long M = (long)in_sizes[1] / 64;
    int grid = (int)((M + 255) / 256);

    cudaFuncSetAttribute(coupling_mma_kernel,
                         cudaFuncAttributeMaxDynamicSharedMemorySize, SMEM_BYTES);
    coupling_mma_kernel<<<grid, THREADS, SMEM_BYTES>>>(coords, c,
                                                       Wx1, bx1, Wx2, bx2,
                                                       Wy1, by1, Wy2, by2,
                                                       out, M);
}

// round 6
// speedup vs baseline: 1.2189x; 1.2189x over previous
#include <cuda_runtime.h>
#include <math.h>
#include <cstdint>

#define THREADS 128

typedef unsigned long long u64;
typedef unsigned int u32;

// ---------------- f32x2 helpers ----------------
__device__ __forceinline__ u64 ffma2(u64 a, u64 b, u64 c) {
    u64 d; asm("fma.rn.f32x2 %0, %1, %2, %3;" : "=l"(d) : "l"(a), "l"(b), "l"(c)); return d;
}
__device__ __forceinline__ u64 mul2(u64 a, u64 b) {
    u64 d; asm("mul.rn.f32x2 %0, %1, %2;" : "=l"(d) : "l"(a), "l"(b)); return d;
}
__device__ __forceinline__ u64 dup2(float x) {
    u64 d; unsigned u = __float_as_uint(x);
    asm("mov.b64 %0, {%1, %2};" : "=l"(d) : "r"(u), "r"(u)); return d;
}
__device__ __forceinline__ u64 pack2(float a, float b) {
    u64 d; asm("mov.b64 %0, {%1, %2};" : "=l"(d) : "r"(__float_as_uint(a)), "r"(__float_as_uint(b))); return d;
}
__device__ __forceinline__ void unpack2(u64 v, float &lo, float &hi) {
    unsigned a, b; asm("mov.b64 {%0, %1}, %2;" : "=r"(a), "=r"(b) : "l"(v));
    lo = __uint_as_float(a); hi = __uint_as_float(b);
}
__device__ __forceinline__ u32 f2tf32(float f) {
    u32 r; asm("cvt.rna.tf32.f32 %0, %1;" : "=r"(r) : "f"(f)); return r;
}

// mma.sync m16n8k8 tf32 (portable sm_80+ path; runs on tensor pipe)
__device__ __forceinline__ void mma8r(float* acc, u32 a0, u32 a1, u32 a2, u32 a3, u64 b) {
    u32 b0 = (u32)b, b1 = (u32)(b >> 32);
    asm volatile("mma.sync.aligned.m16n8k8.row.col.f32.tf32.tf32.f32 "
                 "{%0,%1,%2,%3}, {%4,%5,%6,%7}, {%8,%9}, {%0,%1,%2,%3};"
                 : "+f"(acc[0]), "+f"(acc[1]), "+f"(acc[2]), "+f"(acc[3])
                 : "r"(a0), "r"(a1), "r"(a2), "r"(a3), "r"(b0), "r"(b1));
}

__device__ __forceinline__ float qredf(float v) {
    v += __shfl_xor_sync(0xffffffffu, v, 1);
    v += __shfl_xor_sync(0xffffffffu, v, 2);
    return v;
}

__device__ __forceinline__ float sel4(int t, float4 f) {
    return t == 0 ? f.x : (t == 1 ? f.y : (t == 2 ? f.z : f.w));
}

// ---------------- smem layout (bytes) ----------------
#define SM_Q     0        /* float4[128]               2048 */
#define SM_MP2   2048     /* ulonglong2[128] (H0,H1)   2048 */
#define SM_W2C   4096     /* ulonglong2[64]            1024 */
#define SM_BEXT  5120     /* u64[256*4]                8192 */
#define SM_A     16384    /* u32 tf32 [128][64] xor-swz 32768 */
#define SM_BP    49152    /* u64 [256][32] xor-swz     65536 */
#define SMEM_BYTES 114688

#define LK_A 0.84852813742385703f  /* 0.6*sqrt(2) */
#define LK_B 0.56568542494923801f  /* 0.4*sqrt(2) */

__global__ __launch_bounds__(THREADS, 2)
void coupling_mma_kernel(const float* __restrict__ coords,
                         const float* __restrict__ c,
                         const float* __restrict__ Wx1, const float* __restrict__ bx1,
                         const float* __restrict__ Wx2, const float* __restrict__ bx2,
                         const float* __restrict__ Wy1, const float* __restrict__ by1,
                         const float* __restrict__ Wy2, const float* __restrict__ by2,
                         float* __restrict__ out, long M)
{
    extern __shared__ char smem[];
    const int tid  = threadIdx.x;
    const int lane = tid & 31;
    const int warp = tid >> 5;
    const int g    = lane >> 2;     // 0..7
    const int tq   = lane & 3;      // 0..3
    const long base = (long)blockIdx.x * 128;

    const float s1 = 1.0f / sqrtf(68.0f);
    const float s2 = 1.0f / sqrtf(192.0f);

    float4* QS = (float4*)(smem + SM_Q);
    ulonglong2* MP2 = (ulonglong2*)(smem + SM_MP2);
    ulonglong2* W2C = (ulonglong2*)(smem + SM_W2C);
    u64*    BEXT = (u64*)(smem + SM_BEXT);
    u32*    AS = (u32*)(smem + SM_A);
    u64*    BP = (u64*)(smem + SM_BP);

    // ---------- staging ----------
    // A: c[128 x 64] -> tf32 bits, layout row*64 + (k ^ ((row&7)<<2))
    #pragma unroll
    for (int i = 0; i < 16; i++) {
        int idx = tid + i * THREADS;          // float4 index
        int row = idx >> 4;
        int k4  = (idx & 15) << 2;
        long gr = base + row;
        float4 v = make_float4(0.f, 0.f, 0.f, 0.f);
        if (gr < M) v = *(const float4*)(c + gr * 64 + k4);
        uint4 tv = { f2tf32(v.x), f2tf32(v.y), f2tf32(v.z), f2tf32(v.w) };
        *(uint4*)(AS + row * 64 + (k4 ^ ((row & 7) << 2))) = tv;
    }
    // Bpack: n = output j (0..255), pair index j8 = kk*4+t -> (W[n][k0], W[n][k0+4])
    #pragma unroll
    for (int i = 0; i < 64; i++) {
        int idx = tid + i * THREADS;          // u64 element index 0..8191
        int n  = idx >> 5;
        int j8 = idx & 31;
        int kk = j8 >> 2, t = j8 & 3;
        int k0 = kk * 8 + t;
        const float* Wg = (n < 128) ? Wx1 : Wy1;
        int row = n & 127;
        u32 lo = f2tf32(Wg[row * 68 + 4 + k0] * s1);
        u32 hi = f2tf32(Wg[row * 68 + 4 + k0 + 4] * s1);
        BP[n * 32 + (j8 ^ ((n & 3) << 2))] = ((u64)hi << 32) | lo;
    }
    // BEXT: extension K-block (k=0..3: W1 sin cols; k=4: bias; k=5..7: 0)
    // per n, slot s holds column tq = s ^ (n&3): (W1s[tq][n], tq==0 ? b1[n] : 0)
    #pragma unroll
    for (int i = 0; i < 8; i++) {
        int idx = tid + i * THREADS;          // 0..1023
        int n = idx >> 2;
        int s = idx & 3;
        int t = s ^ (n & 3);
        const float* Wg  = (n < 128) ? Wx1 : Wy1;
        const float* b1g = (n < 128) ? bx1 : by1;
        int row = n & 127;
        u32 lo = f2tf32(Wg[row * 68 + t] * s1);
        u32 hi = (t == 0) ? f2tf32(b1g[row]) : 0u;
        BEXT[idx] = ((u64)hi << 32) | lo;
    }
    // MP2: jp -> (H0, H1) only
    {
        int jp = tid;
        int j0 = 2 * jp;
        int st = j0 >> 7;
        int jj0 = j0 & 127, jj1 = jj0 + 1;
        const float* W2g = st ? Wy2 : Wx2;
        ulonglong2 p;
        p.x = pack2(W2g[jj0] * s2, W2g[jj1] * s2);
        p.y = pack2(W2g[192 + jj0] * s2, W2g[192 + jj1] * s2);
        MP2[jp] = p;
    }
    if (tid < 64) {
        int k = tid;
        ulonglong2 w;
        w.x = pack2(Wx2[128 + k] * s2, Wx2[192 + 128 + k] * s2);
        w.y = pack2(Wy2[128 + k] * s2, Wy2[192 + 128 + k] * s2);
        W2C[k] = w;
    }
    __syncthreads();

    // ---------- per-row q = c @ W2c (+ b2), row = tid ----------
    {
        int row = tid;
        int swz = (row & 7) << 2;
        u64 qx = pack2(0.f, 0.f), qy = qx;
        #pragma unroll
        for (int k4 = 0; k4 < 64; k4 += 4) {
            uint4 cv = *(uint4*)(AS + row * 64 + (k4 ^ swz));
            float cf[4] = { __uint_as_float(cv.x), __uint_as_float(cv.y),
                            __uint_as_float(cv.z), __uint_as_float(cv.w) };
            #pragma unroll
            for (int q = 0; q < 4; q++) {
                ulonglong2 w = W2C[k4 + q];
                u64 cd = dup2(cf[q]);
                qx = ffma2(cd, w.x, qx);
                qy = ffma2(cd, w.y, qy);
            }
        }
        float qx0, qx1, qy0, qy1;
        unpack2(qx, qx0, qx1); unpack2(qy, qy0, qy1);
        QS[tid] = make_float4(qx0 + bx2[0], qx1 + bx2[1], qy0 + by2[0], qy1 + by2[1]);
    }
    __syncwarp();

    // ---------- A fragments (cached, reused both stages) ----------
    u32 afr[2][8][4];
    {
        const int swz = g << 2;   // rows used always have row&7 == g
        #pragma unroll
        for (int mt = 0; mt < 2; mt++) {
            int r0 = warp * 32 + mt * 16 + g;
            #pragma unroll
            for (int kk = 0; kk < 8; kk++) {
                int k0 = kk * 8 + tq;
                afr[mt][kk][0] = AS[r0 * 64 + (k0 ^ swz)];
                afr[mt][kk][1] = AS[(r0 + 8) * 64 + (k0 ^ swz)];
                afr[mt][kk][2] = AS[r0 * 64 + ((k0 + 4) ^ swz)];
                afr[mt][kk][3] = AS[(r0 + 8) * 64 + ((k0 + 4) ^ swz)];
            }
        }
    }

    // rows owned by this thread (quad-redundant)
    int R[4];
    #pragma unroll
    for (int ri = 0; ri < 4; ri++) R[ri] = warp * 32 + ri * 8 + g;

    float cin[4], cup[4], lsum[4];
    #pragma unroll
    for (int ri = 0; ri < 4; ri++) {
        long rr = base + R[ri];
        float2 xy = make_float2(0.f, 0.f);
        if (rr < M) xy = ((const float2*)coords)[rr];
        cin[ri] = xy.x; cup[ri] = xy.y; lsum[ri] = 0.0f;
    }

    const u64 lkA = dup2(LK_A), lkB = dup2(LK_B);
    const u64 ABSM = 0x7FFFFFFF7FFFFFFFull;
    const u32 eone = (tq == 0) ? 0x3F800000u : 0u;  // feat[tq+4] = (k==4 -> 1)
    const int eswz = tq ^ (g & 3);                  // BEXT slot for this thread

    for (int st = 0; st < 2; st++) {
        // per-row sin features (registers; quad-uniform inputs)
        float4 fs[4];
        #pragma unroll
        for (int ri = 0; ri < 4; ri++) {
            float a = cin[ri] * 0.1f, sa, ca;
            sincosf(a, &sa, &ca);
            fs[ri] = make_float4(sa, 2.0f * sa * ca, ca, 1.0f - 2.0f * sa * sa);
        }
        // extension A fragment per m-tile: a0=feat[tq](row r0), a1=feat[tq](row r0+8)
        u32 e0[2], e1[2];
        #pragma unroll
        for (int mt = 0; mt < 2; mt++) {
            e0[mt] = f2tf32(sel4(tq, fs[2 * mt]));
            e1[mt] = f2tf32(sel4(tq, fs[2 * mt + 1]));
        }

        u64 po0[4], po1[4];
        #pragma unroll
        for (int ri = 0; ri < 4; ri++) { po0[ri] = pack2(0.f, 0.f); po1[ri] = po0[ri]; }

        for (int chunk = 0; chunk < 4; chunk++) {
            int nbase = st * 16 + chunk * 4;
            float acc[2][4][4];
            #pragma unroll
            for (int mt = 0; mt < 2; mt++)
                #pragma unroll
                for (int nt = 0; nt < 4; nt++)
                    #pragma unroll
                    for (int q = 0; q < 4; q++) acc[mt][nt][q] = 0.0f;

            // extension step first (independent of main kk chain)
            #pragma unroll
            for (int nt = 0; nt < 4; nt++) {
                int n = (nbase + nt) * 8 + g;
                u64 be = BEXT[n * 4 + eswz];
                mma8r(acc[0][nt], e0[0], e1[0], eone, eone, be);
                mma8r(acc[1][nt], e0[1], e1[1], eone, eone, be);
            }

            #pragma unroll
            for (int kk = 0; kk < 8; kk++) {
                u64 bfr[4];
                #pragma unroll
                for (int nt = 0; nt < 4; nt++) {
                    int n = (nbase + nt) * 8 + g;
                    int j8 = (kk * 4 + tq) ^ ((n & 3) << 2);
                    bfr[nt] = BP[n * 32 + j8];
                }
                #pragma unroll
                for (int nt = 0; nt < 4; nt++) {
                    mma8r(acc[0][nt], afr[0][kk][0], afr[0][kk][1], afr[0][kk][2], afr[0][kk][3], bfr[nt]);
                    mma8r(acc[1][nt], afr[1][kk][0], afr[1][kk][1], afr[1][kk][2], afr[1][kk][3], bfr[nt]);
                }
            }

            // epilogue: leaky + dot into o partials (bias+sin already in acc)
            #pragma unroll
            for (int nt = 0; nt < 4; nt++) {
                int jp = st * 64 + chunk * 16 + nt * 4 + tq;
                ulonglong2 P = MP2[jp];
                u64 H0 = P.x, H1 = P.y;
                #pragma unroll
                for (int mt = 0; mt < 2; mt++) {
                    #pragma unroll
                    for (int h = 0; h < 2; h++) {
                        int ri = mt * 2 + h;
                        u64 v = pack2(acc[mt][nt][2 * h + 0], acc[mt][nt][2 * h + 1]);
                        u64 av = v & ABSM;
                        u64 hh = ffma2(lkA, v, mul2(lkB, av));
                        po0[ri] = ffma2(hh, H0, po0[ri]);
                        po1[ri] = ffma2(hh, H1, po1[ri]);
                    }
                }
            }
        }

        // reduce + coordinate update
        #pragma unroll
        for (int ri = 0; ri < 4; ri++) {
            float a0, a1, b0, b1;
            unpack2(po0[ri], a0, a1);
            unpack2(po1[ri], b0, b1);
            float o0 = qredf(a0 + a1);
            float o1 = qredf(b0 + b1);
            float4 qv = QS[R[ri]];
            o0 += st ? qv.z : qv.x;
            o1 += st ? qv.w : qv.y;
            float ls = fminf(fmaxf(o0, -5.0f), 5.0f);
            float up_new = cup[ri] * __expf(ls) + o1;
            lsum[ri] += ls;
            cup[ri] = cin[ri];
            cin[ri] = up_new;
        }
    }

    // after stage 1: cin = x_final, cup = y_final. tq==0 lanes store directly.
    if (tq == 0) {
        #pragma unroll
        for (int ri = 0; ri < 4; ri++) {
            long rr = base + R[ri];
            if (rr < M) {
                ((float2*)out)[rr] = make_float2(cin[ri], cup[ri]);
                out[2 * M + rr] = lsum[ri];
            }
        }
    }
}

extern "C" void kernel_launch(void* const* d_in, const int* in_sizes, int n_in,
                              void* d_out, int out_size) {
    const float* coords = (const float*)d_in[0];
    const float* c      = (const float*)d_in[1];
    const float* Wx1    = (const float*)d_in[2];
    const float* bx1    = (const float*)d_in[3];
    const float* Wx2    = (const float*)d_in[4];
    const float* bx2    = (const float*)d_in[5];
    const float* Wy1    = (const float*)d_in[6];
    const float* by1    = (const float*)d_in[7];
    const float* Wy2    = (const float*)d_in[8];
    const float* by2    = (const float*)d_in[9];
    float* out = (float*)d_out;

    long M = (long)in_sizes[1] / 64;
    int grid = (int)((M + 127) / 128);

    cudaFuncSetAttribute(coupling_mma_kernel,
                         cudaFuncAttributeMaxDynamicSharedMemorySize, SMEM_BYTES);
    coupling_mma_kernel<<<grid, THREADS, SMEM_BYTES>>>(coords, c,
                                                       Wx1, bx1, Wx2, bx2,
                                                       Wy1, by1, Wy2, by2,
                                                       out, M);
}